// round 1
// baseline (speedup 1.0000x reference)
#include <cuda_runtime.h>
#include <cuda_bf16.h>

#define NFFT      16384
#define LOGN      14
#define LSEQ      8192
#define NTHREADS  1024
#define DCH       256
#define NROWS     2048   // B * D = 8 * 256

// Twiddle table: W^k = exp(-2*pi*i*k/NFFT), k in [0, NFFT/2)
__device__ float2 d_tw[NFFT / 2];

__global__ void twiddle_kernel() {
    int k = blockIdx.x * blockDim.x + threadIdx.x;
    if (k < NFFT / 2) {
        double a = -2.0 * 3.141592653589793238462643383279502884 * (double)k / (double)NFFT;
        d_tw[k] = make_float2((float)cos(a), (float)sin(a));
    }
}

__device__ __forceinline__ float2 cmul(float2 a, float2 b) {
    return make_float2(fmaf(a.x, b.x, -a.y * b.y), fmaf(a.x, b.y, a.y * b.x));
}

extern "C" __global__ void __launch_bounds__(NTHREADS, 1)
fftconv_kernel(const float* __restrict__ x, const float* __restrict__ f,
               const int* __restrict__ pos32, float* __restrict__ out) {
    extern __shared__ float2 sm[];  // NFFT float2 = 128 KB
    const int row = blockIdx.x;
    const int b   = row / DCH;
    const int tid = threadIdx.x;
    const float* __restrict__ xr = x + (size_t)row * LSEQ;
    const float* __restrict__ fr = f + (size_t)row * LSEQ;

    // ---- Detect positions dtype: int64 vs int32 (jax x64 may be off) ----
    // For int64 little-endian, every high word is 0 or -1 (values in [-1, L)).
    bool is64 = true;
    #pragma unroll
    for (int i = 0; i < 64; i++) {
        int hi = __ldg(pos32 + 2 * i + 1);
        if (hi != 0 && hi != -1) is64 = false;
    }

    // ---- Load: real = x, imag = filter; zero-pad to NFFT ----
    #pragma unroll
    for (int jj = 0; jj < LSEQ / NTHREADS; jj++) {
        int i = tid + jj * NTHREADS;
        sm[i] = make_float2(xr[i], fr[i]);
    }
    #pragma unroll
    for (int jj = 0; jj < LSEQ / NTHREADS; jj++) {
        int i = LSEQ + tid + jj * NTHREADS;
        sm[i] = make_float2(0.f, 0.f);
    }
    __syncthreads();

    // ---- Forward FFT: radix-2 DIF (natural -> bit-reversed) ----
    for (int s = 0; s < LOGN; s++) {
        int hb   = LOGN - 1 - s;
        int half = 1 << hb;
        #pragma unroll
        for (int jj = 0; jj < (NFFT / 2) / NTHREADS; jj++) {
            int j  = tid + jj * NTHREADS;
            int p  = j & (half - 1);
            int i0 = ((j >> hb) << (hb + 1)) | p;
            int i1 = i0 + half;
            float2 a  = sm[i0];
            float2 bb = sm[i1];
            float2 w  = d_tw[p << s];
            sm[i0] = make_float2(a.x + bb.x, a.y + bb.y);
            float2 d = make_float2(a.x - bb.x, a.y - bb.y);
            sm[i1] = cmul(d, w);
        }
        __syncthreads();
    }

    // ---- Pointwise: split two-for-one, multiply, restore conj symmetry ----
    // Data is bit-reversed; pair k <-> N-k via __brev indexing.
    // Output scale: result = circconv / n, via IFFT_noscale => scale = 1/n^2.
    const float scale = 1.0f / ((float)NFFT * (float)NFFT);
    for (int k = tid; k <= NFFT / 2; k += NTHREADS) {
        int kk = (NFFT - k) & (NFFT - 1);
        int p1 = __brev(k)  >> (32 - LOGN);
        int p2 = __brev(kk) >> (32 - LOGN);
        float2 z1 = sm[p1];
        float2 z2 = sm[p2];
        // X = (Z[k] + conj(Z[-k]))/2 ; F = (Z[k] - conj(Z[-k]))/(2i)
        float2 X = make_float2(0.5f * (z1.x + z2.x), 0.5f * (z1.y - z2.y));
        float2 F = make_float2(0.5f * (z1.y + z2.y), 0.5f * (z2.x - z1.x));
        float2 Y = cmul(X, F);
        Y.x *= scale; Y.y *= scale;
        sm[p1] = Y;
        sm[p2] = make_float2(Y.x, -Y.y);  // self-pairs (k=0, N/2) have Y.y==0 exactly
    }
    __syncthreads();

    // ---- Inverse FFT: radix-2 DIT (bit-reversed -> natural), unnormalized ----
    for (int s = 0; s < LOGN; s++) {
        int half = 1 << s;
        #pragma unroll
        for (int jj = 0; jj < (NFFT / 2) / NTHREADS; jj++) {
            int j  = tid + jj * NTHREADS;
            int p  = j & (half - 1);
            int i0 = ((j >> s) << (s + 1)) | p;
            int i1 = i0 + half;
            float2 a  = sm[i0];
            float2 bb = sm[i1];
            float2 w  = d_tw[p << (LOGN - 1 - s)];
            w.y = -w.y;  // conjugate twiddle for inverse
            float2 t = cmul(bb, w);
            sm[i0] = make_float2(a.x + t.x, a.y + t.y);
            sm[i1] = make_float2(a.x - t.x, a.y - t.y);
        }
        __syncthreads();
    }

    // ---- Store first LSEQ real samples, masked by positions != -1 ----
    #pragma unroll
    for (int jj = 0; jj < LSEQ / NTHREADS; jj++) {
        int l = tid + jj * NTHREADS;
        bool valid;
        if (is64) {
            long long v = ((const long long*)pos32)[(size_t)b * LSEQ + l];
            valid = (v != -1LL);
        } else {
            valid = (pos32[(size_t)b * LSEQ + l] != -1);
        }
        out[(size_t)row * LSEQ + l] = valid ? sm[l].x : 0.0f;
    }
}

extern "C" void kernel_launch(void* const* d_in, const int* in_sizes, int n_in,
                              void* d_out, int out_size) {
    const float* x   = (const float*)d_in[0];
    const float* f   = (const float*)d_in[1];
    const int*   pos = (const int*)d_in[2];
    float*       out = (float*)d_out;

    cudaFuncSetAttribute(fftconv_kernel,
                         cudaFuncAttributeMaxDynamicSharedMemorySize,
                         NFFT * sizeof(float2));

    twiddle_kernel<<<(NFFT / 2 + 255) / 256, 256>>>();
    fftconv_kernel<<<NROWS, NTHREADS, NFFT * sizeof(float2)>>>(x, f, pos, out);
}

// round 2
// speedup vs baseline: 1.5185x; 1.5185x over previous
#include <cuda_runtime.h>
#include <cuda_bf16.h>

#define NFFT   16384
#define LOGN   14
#define LSEQ   8192
#define NT     1024
#define DCH    256
#define NROWS  2048

// Twiddle table: W^k = exp(-2*pi*i*k/NFFT), k in [0, NFFT/2)
__device__ float2 d_tw[NFFT / 2];

__global__ void twiddle_kernel() {
    int k = blockIdx.x * blockDim.x + threadIdx.x;
    if (k < NFFT / 2) {
        double a = -2.0 * 3.141592653589793238462643383279502884 * (double)k / (double)NFFT;
        d_tw[k] = make_float2((float)cos(a), (float)sin(a));
    }
}

__device__ __forceinline__ float2 cmul(float2 a, float2 b) {
    return make_float2(fmaf(a.x, b.x, -a.y * b.y), fmaf(a.x, b.y, a.y * b.x));
}
// a * conj(b)
__device__ __forceinline__ float2 cmulc(float2 a, float2 b) {
    return make_float2(fmaf(a.x, b.x,  a.y * b.y), fmaf(a.y, b.x, -a.x * b.y));
}
// bank swizzle: conflict-free for strides 1, 4, 64, 1024 (verified per half-warp)
__device__ __forceinline__ int sw(int i) { return i ^ ((i >> 4) & 15); }

// C16[k] = exp(-2*pi*i*k/16), k = 0..7 (compile-time constants)
__device__ __forceinline__ float2 twmul(float2 wp, int k) {
    // returns wp * C16[k]; k is compile-time after unroll
    constexpr float cx[8] = { 1.0f,  0.92387953251128674f,  0.70710678118654752f,  0.38268343236508977f,
                              0.0f, -0.38268343236508977f, -0.70710678118654752f, -0.92387953251128674f };
    constexpr float cy[8] = { 0.0f, -0.38268343236508977f, -0.70710678118654752f, -0.92387953251128674f,
                             -1.0f, -0.92387953251128674f, -0.70710678118654752f, -0.38268343236508977f };
    if (k == 0) return wp;
    if (k == 4) return make_float2(wp.y, -wp.x);   // * (-i)
    return cmul(wp, make_float2(cx[k], cy[k]));
}

// Forward DIF: 4 stages over 16 register-resident elements with base twiddle w.
// Global stage s = s_base + u; tw = w^(2^u) * C16[m << u].
__device__ __forceinline__ void dif4(float2 v[16], float2 w) {
    float2 wp = w;
    #pragma unroll
    for (int u = 0; u < 4; u++) {
        const int h  = 8 >> u;
        const int nb = 1 << u;
        #pragma unroll
        for (int b = 0; b < nb; b++) {
            #pragma unroll
            for (int m = 0; m < h; m++) {
                int j0 = b * 2 * h + m, j1 = j0 + h;
                float2 a = v[j0], c = v[j1];
                v[j0] = make_float2(a.x + c.x, a.y + c.y);
                float2 d = make_float2(a.x - c.x, a.y - c.y);
                v[j1] = cmul(d, twmul(wp, m << u));
            }
        }
        wp = cmul(wp, wp);
    }
}

// Inverse DIT: 4 stages; stage u uses conj(w^(2^(3-u)) * C16[m << (3-u)]).
__device__ __forceinline__ void dit4(float2 v[16], float2 w) {
    float2 wp[4];
    wp[0] = w;
    wp[1] = cmul(wp[0], wp[0]);
    wp[2] = cmul(wp[1], wp[1]);
    wp[3] = cmul(wp[2], wp[2]);
    #pragma unroll
    for (int u = 0; u < 4; u++) {
        const int h  = 1 << u;
        const int nb = 8 >> u;
        #pragma unroll
        for (int b = 0; b < nb; b++) {
            #pragma unroll
            for (int m = 0; m < h; m++) {
                int j0 = b * 2 * h + m, j1 = j0 + h;
                float2 z = twmul(wp[3 - u], m << (3 - u));
                float2 a = v[j0], c = v[j1];
                float2 t = cmulc(c, z);                 // c * conj(z)
                v[j0] = make_float2(a.x + t.x, a.y + t.y);
                v[j1] = make_float2(a.x - t.x, a.y - t.y);
            }
        }
    }
}

// Forward stages 12,13 (local distances 2, 1); twiddles are {1, -i}, {1}.
__device__ __forceinline__ void dif_last2(float2 v[16]) {
    #pragma unroll
    for (int b = 0; b < 4; b++) {
        #pragma unroll
        for (int m = 0; m < 2; m++) {
            int j0 = b * 4 + m, j1 = j0 + 2;
            float2 a = v[j0], c = v[j1];
            v[j0] = make_float2(a.x + c.x, a.y + c.y);
            float2 d = make_float2(a.x - c.x, a.y - c.y);
            v[j1] = (m == 0) ? d : make_float2(d.y, -d.x);  // * (-i)
        }
    }
    #pragma unroll
    for (int b = 0; b < 8; b++) {
        int j0 = 2 * b, j1 = j0 + 1;
        float2 a = v[j0], c = v[j1];
        v[j0] = make_float2(a.x + c.x, a.y + c.y);
        v[j1] = make_float2(a.x - c.x, a.y - c.y);
    }
}

// Inverse stages 0,1; twiddles {1}, {1, +i}.
__device__ __forceinline__ void dit_first2(float2 v[16]) {
    #pragma unroll
    for (int b = 0; b < 8; b++) {
        int j0 = 2 * b, j1 = j0 + 1;
        float2 a = v[j0], c = v[j1];
        v[j0] = make_float2(a.x + c.x, a.y + c.y);
        v[j1] = make_float2(a.x - c.x, a.y - c.y);
    }
    #pragma unroll
    for (int b = 0; b < 4; b++) {
        #pragma unroll
        for (int m = 0; m < 2; m++) {
            int j0 = b * 4 + m, j1 = j0 + 2;
            float2 a = v[j0], c = v[j1];
            float2 t = (m == 0) ? c : make_float2(-c.y, c.x);  // * (+i)
            v[j0] = make_float2(a.x + t.x, a.y + t.y);
            v[j1] = make_float2(a.x - t.x, a.y - t.y);
        }
    }
}

extern "C" __global__ void __launch_bounds__(NT, 1)
fftconv_kernel(const float* __restrict__ x, const float* __restrict__ f,
               const int* __restrict__ pos32, float* __restrict__ out) {
    extern __shared__ float2 sm[];   // NFFT float2 = 128 KB
    const int row = blockIdx.x;
    const int b   = row / DCH;
    const int t   = threadIdx.x;
    const float* __restrict__ xr = x + (size_t)row * LSEQ;
    const float* __restrict__ fr = f + (size_t)row * LSEQ;

    // Detect positions dtype: int64 vs int32 (jax x64 may be off).
    bool is64 = true;
    #pragma unroll
    for (int i = 0; i < 64; i++) {
        int hi = __ldg(pos32 + 2 * i + 1);
        if (hi != 0 && hi != -1) is64 = false;
    }

    float2 v[16];

    // ---- Load (group-A pattern: e = t + 1024j), pack z = x + i*f, zero-pad ----
    #pragma unroll
    for (int j = 0; j < 8; j++) {
        int e = t + 1024 * j;
        v[j] = make_float2(xr[e], fr[e]);
    }
    #pragma unroll
    for (int j = 8; j < 16; j++) v[j] = make_float2(0.f, 0.f);

    // ---- Forward FFT (DIF, natural -> bit-reversed) ----
    dif4(v, d_tw[t]);                                  // stages 0-3, stride 1024
    #pragma unroll
    for (int j = 0; j < 16; j++) sm[sw(t + 1024 * j)] = v[j];
    __syncthreads();
    {
        int g = t >> 6, r = t & 63, base = g * 1024 + r;
        #pragma unroll
        for (int j = 0; j < 16; j++) v[j] = sm[sw(base + 64 * j)];
        dif4(v, d_tw[r << 4]);                         // stages 4-7, stride 64
        #pragma unroll
        for (int j = 0; j < 16; j++) sm[sw(base + 64 * j)] = v[j];
    }
    __syncthreads();
    {
        int h = t >> 2, q = t & 3, base = h * 64 + q;
        #pragma unroll
        for (int j = 0; j < 16; j++) v[j] = sm[sw(base + 4 * j)];
        dif4(v, d_tw[q << 8]);                         // stages 8-11, stride 4
        #pragma unroll
        for (int j = 0; j < 16; j++) sm[sw(base + 4 * j)] = v[j];
    }
    __syncthreads();
    {
        int base = t * 16;
        #pragma unroll
        for (int j = 0; j < 16; j++) v[j] = sm[sw(base + j)];
        dif_last2(v);                                  // stages 12-13, stride 1
        #pragma unroll
        for (int j = 0; j < 16; j++) sm[sw(base + j)] = v[j];
    }
    __syncthreads();

    // ---- Pointwise in bit-reversed domain: two-for-one split + product ----
    const float scale = 1.0f / ((float)NFFT * (float)NFFT);
    for (int k = t; k <= NFFT / 2; k += NT) {
        int kk = (NFFT - k) & (NFFT - 1);
        int p1 = sw(__brev(k)  >> (32 - LOGN));
        int p2 = sw(__brev(kk) >> (32 - LOGN));
        float2 z1 = sm[p1];
        float2 z2 = sm[p2];
        float2 X = make_float2(0.5f * (z1.x + z2.x), 0.5f * (z1.y - z2.y));
        float2 F = make_float2(0.5f * (z1.y + z2.y), 0.5f * (z2.x - z1.x));
        float2 Y = cmul(X, F);
        Y.x *= scale; Y.y *= scale;
        sm[p1] = Y;
        sm[p2] = make_float2(Y.x, -Y.y);
    }
    __syncthreads();

    // ---- Inverse FFT (DIT, bit-reversed -> natural, unnormalized) ----
    {
        int base = t * 16;
        #pragma unroll
        for (int j = 0; j < 16; j++) v[j] = sm[sw(base + j)];
        dit_first2(v);                                 // stages 0-1, stride 1
        #pragma unroll
        for (int j = 0; j < 16; j++) sm[sw(base + j)] = v[j];
    }
    __syncthreads();
    {
        int h = t >> 2, q = t & 3, base = h * 64 + q;
        #pragma unroll
        for (int j = 0; j < 16; j++) v[j] = sm[sw(base + 4 * j)];
        dit4(v, d_tw[q << 8]);                         // stages 2-5, stride 4
        #pragma unroll
        for (int j = 0; j < 16; j++) sm[sw(base + 4 * j)] = v[j];
    }
    __syncthreads();
    {
        int g = t >> 6, r = t & 63, base = g * 1024 + r;
        #pragma unroll
        for (int j = 0; j < 16; j++) v[j] = sm[sw(base + 64 * j)];
        dit4(v, d_tw[r << 4]);                         // stages 6-9, stride 64
        #pragma unroll
        for (int j = 0; j < 16; j++) sm[sw(base + 64 * j)] = v[j];
    }
    __syncthreads();
    {
        #pragma unroll
        for (int j = 0; j < 16; j++) v[j] = sm[sw(t + 1024 * j)];
        dit4(v, d_tw[t]);                              // stages 10-13, stride 1024

        // ---- Store first LSEQ real samples (elements e = t + 1024j, j < 8) ----
        #pragma unroll
        for (int j = 0; j < 8; j++) {
            int l = t + 1024 * j;
            bool valid;
            if (is64) {
                long long pv = ((const long long*)pos32)[(size_t)b * LSEQ + l];
                valid = (pv != -1LL);
            } else {
                valid = (pos32[(size_t)b * LSEQ + l] != -1);
            }
            out[(size_t)row * LSEQ + l] = valid ? v[j].x : 0.0f;
        }
    }
}

extern "C" void kernel_launch(void* const* d_in, const int* in_sizes, int n_in,
                              void* d_out, int out_size) {
    const float* x   = (const float*)d_in[0];
    const float* f   = (const float*)d_in[1];
    const int*   pos = (const int*)d_in[2];
    float*       out = (float*)d_out;

    cudaFuncSetAttribute(fftconv_kernel,
                         cudaFuncAttributeMaxDynamicSharedMemorySize,
                         NFFT * sizeof(float2));

    twiddle_kernel<<<(NFFT / 2 + 255) / 256, 256>>>();
    fftconv_kernel<<<NROWS, NT, NFFT * sizeof(float2)>>>(x, f, pos, out);
}

// round 3
// speedup vs baseline: 6.6853x; 4.4027x over previous
#include <cuda_runtime.h>
#include <cuda_bf16.h>

#define NFFT   16384
#define LOGN   14
#define LSEQ   8192
#define NT     1024
#define DCH    256
#define NROWS  2048

// Twiddle table: W^k = exp(-2*pi*i*k/NFFT), k in [0, NFFT/2)
__device__ float2 d_tw[NFFT / 2];
// Precomputed output mask (B x L), 1.0 where positions != -1
__device__ float d_mask[8 * LSEQ];

__global__ void twiddle_kernel() {
    int k = blockIdx.x * blockDim.x + threadIdx.x;
    if (k < NFFT / 2) {
        double a = -2.0 * 3.141592653589793238462643383279502884 * (double)k / (double)NFFT;
        d_tw[k] = make_float2((float)cos(a), (float)sin(a));
    }
}

// Detect positions dtype (int64 vs int32; jax x64 may be off) and build mask.
__global__ void mask_kernel(const int* __restrict__ pos32) {
    int i = blockIdx.x * blockDim.x + threadIdx.x;   // 0 .. 65535
    bool is64 = true;
    #pragma unroll
    for (int j = 0; j < 64; j++) {
        int hi = __ldg(pos32 + 2 * j + 1);
        if (hi != 0 && hi != -1) is64 = false;
    }
    bool valid;
    if (is64) valid = (((const long long*)pos32)[i] != -1LL);
    else      valid = (pos32[i] != -1);
    d_mask[i] = valid ? 1.0f : 0.0f;
}

__device__ __forceinline__ float2 cmul(float2 a, float2 b) {
    return make_float2(fmaf(a.x, b.x, -a.y * b.y), fmaf(a.x, b.y, a.y * b.x));
}
// a * conj(b)
__device__ __forceinline__ float2 cmulc(float2 a, float2 b) {
    return make_float2(fmaf(a.x, b.x,  a.y * b.y), fmaf(a.y, b.x, -a.x * b.y));
}
__device__ __forceinline__ float2 mi(float2 z) { return make_float2(z.y, -z.x); }  // z * (-i)
__device__ __forceinline__ int sw(int i) { return i ^ ((i >> 4) & 15); }

#define C16_1 make_float2(0.923879532511286756f, -0.382683432365089772f)
#define C16_2 make_float2(0.707106781186547524f, -0.707106781186547524f)
#define C16_3 make_float2(0.382683432365089772f, -0.923879532511286756f)

// DIF butterfly: a' = a+b ; b' = (a-b)*tw
__device__ __forceinline__ void bf(float2& a, float2& b, float2 tw) {
    float2 s = make_float2(a.x + b.x, a.y + b.y);
    float2 d = make_float2(a.x - b.x, a.y - b.y);
    a = s; b = cmul(d, tw);
}
// DIT butterfly (inverse): t = b*conj(tw) ; a' = a+t ; b' = a-t
__device__ __forceinline__ void bfi(float2& a, float2& b, float2 tw) {
    float2 t = cmulc(b, tw);
    float2 s = make_float2(a.x + t.x, a.y + t.y);
    b = make_float2(a.x - t.x, a.y - t.y);
    a = s;
}

// Forward stages at local distances 4, 2, 1 (shared tail of a radix-16 group).
__device__ __forceinline__ void dif_stages123(float2 v[16], float2 ws2) {
    float2 u = cmul(ws2, C16_2);
    bf(v[0], v[4],  ws2); bf(v[1], v[5],  u); bf(v[2],  v[6],  mi(ws2)); bf(v[3],  v[7],  mi(u));
    bf(v[8], v[12], ws2); bf(v[9], v[13], u); bf(v[10], v[14], mi(ws2)); bf(v[11], v[15], mi(u));
    float2 ws4 = cmul(ws2, ws2);
    #pragma unroll
    for (int b = 0; b < 4; b++) {
        bf(v[4*b],   v[4*b+2], ws4);
        bf(v[4*b+1], v[4*b+3], mi(ws4));
    }
    float2 ws8 = cmul(ws4, ws4);
    #pragma unroll
    for (int b = 0; b < 8; b++) bf(v[2*b], v[2*b+1], ws8);
}

// Full 4-stage forward group, base twiddle w (distances 8,4,2,1).
__device__ __forceinline__ void dif4(float2 v[16], float2 w) {
    float2 w1 = cmul(w, C16_1), w2 = cmul(w, C16_2), w3 = cmul(w, C16_3);
    bf(v[0], v[8],  w);     bf(v[1], v[9],  w1);     bf(v[2], v[10], w2);     bf(v[3], v[11], w3);
    bf(v[4], v[12], mi(w)); bf(v[5], v[13], mi(w1)); bf(v[6], v[14], mi(w2)); bf(v[7], v[15], mi(w3));
    dif_stages123(v, cmul(w, w));
}

// First forward group with v[8..15] == 0 (zero-padding): stage 0 degenerates.
__device__ __forceinline__ void dif4_zero(float2 v[16], float2 w) {
    float2 w1 = cmul(w, C16_1), w2 = cmul(w, C16_2), w3 = cmul(w, C16_3);
    v[8]  = cmul(v[0], w);      v[9]  = cmul(v[1], w1);
    v[10] = cmul(v[2], w2);     v[11] = cmul(v[3], w3);
    v[12] = cmul(v[4], mi(w));  v[13] = cmul(v[5], mi(w1));
    v[14] = cmul(v[6], mi(w2)); v[15] = cmul(v[7], mi(w3));
    dif_stages123(v, cmul(w, w));
}

// Full 4-stage inverse group, base twiddle w (distances 1,2,4,8), conj twiddles.
__device__ __forceinline__ void dit4(float2 v[16], float2 w) {
    float2 ws2 = cmul(w, w), ws4 = cmul(ws2, ws2), ws8 = cmul(ws4, ws4);
    #pragma unroll
    for (int b = 0; b < 8; b++) bfi(v[2*b], v[2*b+1], ws8);
    #pragma unroll
    for (int b = 0; b < 4; b++) {
        bfi(v[4*b],   v[4*b+2], ws4);
        bfi(v[4*b+1], v[4*b+3], mi(ws4));
    }
    float2 u = cmul(ws2, C16_2);
    bfi(v[0], v[4],  ws2); bfi(v[1], v[5],  u); bfi(v[2],  v[6],  mi(ws2)); bfi(v[3],  v[7],  mi(u));
    bfi(v[8], v[12], ws2); bfi(v[9], v[13], u); bfi(v[10], v[14], mi(ws2)); bfi(v[11], v[15], mi(u));
    float2 w1 = cmul(w, C16_1), w2 = cmul(w, C16_2), w3 = cmul(w, C16_3);
    bfi(v[0], v[8],  w);     bfi(v[1], v[9],  w1);     bfi(v[2], v[10], w2);     bfi(v[3], v[11], w3);
    bfi(v[4], v[12], mi(w)); bfi(v[5], v[13], mi(w1)); bfi(v[6], v[14], mi(w2)); bfi(v[7], v[15], mi(w3));
}

// Forward stages 12,13 (local distances 2, 1); twiddles {1, -i}, {1}.
__device__ __forceinline__ void dif_last2(float2 v[16]) {
    #pragma unroll
    for (int b = 0; b < 4; b++) {
        #pragma unroll
        for (int m = 0; m < 2; m++) {
            int j0 = b * 4 + m, j1 = j0 + 2;
            float2 a = v[j0], c = v[j1];
            v[j0] = make_float2(a.x + c.x, a.y + c.y);
            float2 d = make_float2(a.x - c.x, a.y - c.y);
            v[j1] = (m == 0) ? d : make_float2(d.y, -d.x);
        }
    }
    #pragma unroll
    for (int b = 0; b < 8; b++) {
        int j0 = 2 * b, j1 = j0 + 1;
        float2 a = v[j0], c = v[j1];
        v[j0] = make_float2(a.x + c.x, a.y + c.y);
        v[j1] = make_float2(a.x - c.x, a.y - c.y);
    }
}

// Inverse stages 0,1; twiddles {1}, {1, +i}.
__device__ __forceinline__ void dit_first2(float2 v[16]) {
    #pragma unroll
    for (int b = 0; b < 8; b++) {
        int j0 = 2 * b, j1 = j0 + 1;
        float2 a = v[j0], c = v[j1];
        v[j0] = make_float2(a.x + c.x, a.y + c.y);
        v[j1] = make_float2(a.x - c.x, a.y - c.y);
    }
    #pragma unroll
    for (int b = 0; b < 4; b++) {
        #pragma unroll
        for (int m = 0; m < 2; m++) {
            int j0 = b * 4 + m, j1 = j0 + 2;
            float2 a = v[j0], c = v[j1];
            float2 t = (m == 0) ? c : make_float2(-c.y, c.x);
            v[j0] = make_float2(a.x + t.x, a.y + t.y);
            v[j1] = make_float2(a.x - t.x, a.y - t.y);
        }
    }
}

extern "C" __global__ void __launch_bounds__(NT, 1)
fftconv_kernel(const float* __restrict__ x, const float* __restrict__ f,
               float* __restrict__ out) {
    extern __shared__ float2 sm[];   // NFFT float2 = 128 KB
    const int row = blockIdx.x;
    const int b   = row / DCH;
    const int t   = threadIdx.x;
    const float* __restrict__ xr = x + (size_t)row * LSEQ;
    const float* __restrict__ fr = f + (size_t)row * LSEQ;

    float2 v[16];

    // ---- Load (pattern e = t + 1024j), pack z = x + i*f; upper half zero ----
    #pragma unroll
    for (int j = 0; j < 8; j++) {
        int e = t + 1024 * j;
        v[j] = make_float2(xr[e], fr[e]);
    }

    // ---- Forward FFT (DIF, natural -> bit-reversed) ----
    dif4_zero(v, d_tw[t]);                             // stages 0-3, stride 1024
    #pragma unroll
    for (int j = 0; j < 16; j++) sm[sw(t + 1024 * j)] = v[j];
    __syncthreads();
    {
        int g = t >> 6, r = t & 63, base = g * 1024 + r;
        #pragma unroll
        for (int j = 0; j < 16; j++) v[j] = sm[sw(base + 64 * j)];
        dif4(v, d_tw[r << 4]);                         // stages 4-7, stride 64
        #pragma unroll
        for (int j = 0; j < 16; j++) sm[sw(base + 64 * j)] = v[j];
    }
    __syncthreads();
    {
        int h = t >> 2, q = t & 3, base = h * 64 + q;
        #pragma unroll
        for (int j = 0; j < 16; j++) v[j] = sm[sw(base + 4 * j)];
        dif4(v, d_tw[q << 8]);                         // stages 8-11, stride 4
        #pragma unroll
        for (int j = 0; j < 16; j++) sm[sw(base + 4 * j)] = v[j];
    }
    __syncthreads();
    {
        int base = t * 16;
        #pragma unroll
        for (int j = 0; j < 16; j++) v[j] = sm[sw(base + j)];
        dif_last2(v);                                  // stages 12-13, stride 1
        #pragma unroll
        for (int j = 0; j < 16; j++) sm[sw(base + j)] = v[j];
    }
    __syncthreads();

    // ---- Pointwise in bit-reversed domain: two-for-one split + product ----
    // Lanes own HIGH bits of k so brev(k) varies in LOW bits -> few bank conflicts.
    const float scale = 1.0f / ((float)NFFT * (float)NFFT);
    {
        int lane = t & 31, wrp = t >> 5;
        #pragma unroll
        for (int m = 0; m < 8; m++) {
            int k  = lane * 256 + wrp * 8 + m;          // covers 0..8191 exactly once
            int kk = (NFFT - k) & (NFFT - 1);
            int p1 = sw(__brev(k)  >> (32 - LOGN));
            int p2 = sw(__brev(kk) >> (32 - LOGN));
            float2 z1 = sm[p1];
            float2 z2 = sm[p2];
            float2 X = make_float2(0.5f * (z1.x + z2.x), 0.5f * (z1.y - z2.y));
            float2 F = make_float2(0.5f * (z1.y + z2.y), 0.5f * (z2.x - z1.x));
            float2 Y = cmul(X, F);
            Y.x *= scale; Y.y *= scale;
            sm[p1] = Y;
            sm[p2] = make_float2(Y.x, -Y.y);
        }
        if (t == 0) {                                   // k = 8192 self-pair, brev = 1
            int p = sw(1);
            float2 z = sm[p];
            sm[p] = make_float2(z.x * z.y * scale, 0.0f);
        }
    }
    __syncthreads();

    // ---- Inverse FFT (DIT, bit-reversed -> natural, unnormalized) ----
    {
        int base = t * 16;
        #pragma unroll
        for (int j = 0; j < 16; j++) v[j] = sm[sw(base + j)];
        dit_first2(v);                                 // stages 0-1, stride 1
        #pragma unroll
        for (int j = 0; j < 16; j++) sm[sw(base + j)] = v[j];
    }
    __syncthreads();
    {
        int h = t >> 2, q = t & 3, base = h * 64 + q;
        #pragma unroll
        for (int j = 0; j < 16; j++) v[j] = sm[sw(base + 4 * j)];
        dit4(v, d_tw[q << 8]);                         // stages 2-5, stride 4
        #pragma unroll
        for (int j = 0; j < 16; j++) sm[sw(base + 4 * j)] = v[j];
    }
    __syncthreads();
    {
        int g = t >> 6, r = t & 63, base = g * 1024 + r;
        #pragma unroll
        for (int j = 0; j < 16; j++) v[j] = sm[sw(base + 64 * j)];
        dit4(v, d_tw[r << 4]);                         // stages 6-9, stride 64
        #pragma unroll
        for (int j = 0; j < 16; j++) sm[sw(base + 64 * j)] = v[j];
    }
    __syncthreads();
    {
        #pragma unroll
        for (int j = 0; j < 16; j++) v[j] = sm[sw(t + 1024 * j)];
        dit4(v, d_tw[t]);                              // stages 10-13, stride 1024

        // ---- Store first LSEQ real samples, masked ----
        #pragma unroll
        for (int j = 0; j < 8; j++) {
            int l = t + 1024 * j;
            out[(size_t)row * LSEQ + l] = d_mask[b * LSEQ + l] * v[j].x;
        }
    }
}

extern "C" void kernel_launch(void* const* d_in, const int* in_sizes, int n_in,
                              void* d_out, int out_size) {
    const float* x   = (const float*)d_in[0];
    const float* f   = (const float*)d_in[1];
    const int*   pos = (const int*)d_in[2];
    float*       out = (float*)d_out;

    cudaFuncSetAttribute(fftconv_kernel,
                         cudaFuncAttributeMaxDynamicSharedMemorySize,
                         NFFT * sizeof(float2));

    twiddle_kernel<<<(NFFT / 2 + 255) / 256, 256>>>();
    mask_kernel<<<(8 * LSEQ) / 256, 256>>>(pos);
    fftconv_kernel<<<NROWS, NT, NFFT * sizeof(float2)>>>(x, f, out);
}